// round 8
// baseline (speedup 1.0000x reference)
#include <cuda_runtime.h>
#include <cuda_fp16.h>
#include <cstdint>

#define G_DATA  262144
#define G_TRUNC 40000
#define NEDGE   1048576
#define FEAT    128
#define EPSV    1e-8f

#define NBLK_DOWN 40     // ceil(G_TRUNC/1024)
#define NBLK_UP   256    // G_DATA/1024

// ---------------- scratch (__device__ globals; no allocation allowed) --------
// INVARIANT: g_cnt_* are zero at entry to kernel_launch. They start zero
// (static init) and the countdown scatter returns them to zero every call.
__device__ __half g_xh[(size_t)G_DATA * FEAT];        // 67 MB fp16 copy of x slice
__device__ __half g_xc[(size_t)G_TRUNC * FEAT];       // 10.2 MB fp16 intermediate
__device__ int   g_cnt_down[G_TRUNC];
__device__ int   g_cnt_up[G_DATA];
__device__ int   g_off_down[G_TRUNC + 1];
__device__ int   g_off_up[G_DATA + 1];
__device__ int   g_bsum_down[NBLK_DOWN];
__device__ int   g_bsum_up[NBLK_UP];
__device__ int2  g_edges_down[NEDGE];                 // (src, w bits) bucketed by dst
__device__ int2  g_edges_up[NEDGE];

// ---------------- CSR build --------------------------------------------------

__global__ void hist_kernel(const int* __restrict__ ddst, const int* __restrict__ udst) {
    int i = blockIdx.x * blockDim.x + threadIdx.x;
    if (i < NEDGE) {
        atomicAdd(&g_cnt_down[ddst[i]], 1);
        atomicAdd(&g_cnt_up[udst[i]], 1);
    }
}

// Per-1024-chunk sums for both arrays in one launch (blocks [0,40)=down).
__global__ void scan_partial_both() {
    __shared__ int red[256];
    int blk = blockIdx.x;
    const int* cnt; int* bsum; int n; int b;
    if (blk < NBLK_DOWN) { cnt = g_cnt_down; bsum = g_bsum_down; n = G_TRUNC; b = blk; }
    else                 { cnt = g_cnt_up;   bsum = g_bsum_up;   n = G_DATA;  b = blk - NBLK_DOWN; }
    int base = b * 1024 + threadIdx.x * 4;
    int s = 0;
#pragma unroll
    for (int j = 0; j < 4; j++) { int i = base + j; if (i < n) s += cnt[i]; }
    red[threadIdx.x] = s;
    __syncthreads();
    for (int off = 128; off > 0; off >>= 1) {
        if (threadIdx.x < off) red[threadIdx.x] += red[threadIdx.x + off];
        __syncthreads();
    }
    if (threadIdx.x == 0) bsum[b] = red[0];
}

// Per-element exclusive scan. Each block redundantly scans the (<=256) block
// sums itself. cnt is left intact (the scatter's countdown cursor consumes it).
__global__ void scan_final_both() {
    int blk = blockIdx.x;
    const int* cnt; int* off; const int* bsum; int n, nblk, b;
    if (blk < NBLK_DOWN) { cnt = g_cnt_down; off = g_off_down; bsum = g_bsum_down;
                           n = G_TRUNC; nblk = NBLK_DOWN; b = blk; }
    else                 { cnt = g_cnt_up;   off = g_off_up;   bsum = g_bsum_up;
                           n = G_DATA;  nblk = NBLK_UP;   b = blk - NBLK_DOWN; }
    int t = threadIdx.x;
    int lane = t & 31, wid = t >> 5;

    __shared__ int s[256];
    int bv = (t < nblk) ? bsum[t] : 0;
    s[t] = bv;
    __syncthreads();
    for (int o = 1; o < 256; o <<= 1) {
        int add = (t >= o) ? s[t - o] : 0;
        __syncthreads();
        s[t] += add;
        __syncthreads();
    }
    int block_off = (b > 0) ? s[b - 1] : 0;
    if (b == 0 && t == 0) off[n] = s[nblk - 1];   // grand total

    int base = b * 1024 + t * 4;
    int v0 = 0, v1 = 0, v2 = 0, v3 = 0;
    if (base + 0 < n) v0 = cnt[base + 0];
    if (base + 1 < n) v1 = cnt[base + 1];
    if (base + 2 < n) v2 = cnt[base + 2];
    if (base + 3 < n) v3 = cnt[base + 3];
    int tsum = v0 + v1 + v2 + v3;
    int x = tsum;
#pragma unroll
    for (int o = 1; o < 32; o <<= 1) {
        int y = __shfl_up_sync(0xffffffffu, x, o);
        if (lane >= o) x += y;
    }
    __shared__ int wsum[8];
    if (lane == 31) wsum[wid] = x;
    __syncthreads();
    if (t == 0) {
        int run = 0;
#pragma unroll
        for (int i = 0; i < 8; i++) { int tmp = wsum[i]; wsum[i] = run; run += tmp; }
    }
    __syncthreads();
    int excl = block_off + wsum[wid] + (x - tsum);
    if (base + 0 < n) off[base + 0] = excl; excl += v0;
    if (base + 1 < n) off[base + 1] = excl; excl += v1;
    if (base + 2 < n) off[base + 2] = excl; excl += v2;
    if (base + 3 < n) off[base + 3] = excl;
}

// Fused scatter + fp32->fp16 convert (launch-count saving; both halves share
// the LTS, so overlap is modest). Countdown cursor leaves cnt at zero.
__global__ void __launch_bounds__(256) scatter_convert_kernel(
    const int* __restrict__ dsrc, const int* __restrict__ ddst,
    const float* __restrict__ dw,
    const int* __restrict__ usrc, const int* __restrict__ udst,
    const float* __restrict__ uw,
    const float* __restrict__ x)
{
    int i = blockIdx.x * blockDim.x + threadIdx.x;

    {
        int d = ddst[i];
        int idx = atomicAdd(&g_cnt_down[d], -1);
        g_edges_down[g_off_down[d] + idx - 1] = make_int2(dsrc[i], __float_as_int(dw[i]));
    }
    {
        int d = udst[i];
        int idx = atomicAdd(&g_cnt_up[d], -1);
        g_edges_up[g_off_up[d] + idx - 1] = make_int2(usrc[i], __float_as_int(uw[i]));
    }

    const float4* x4 = reinterpret_cast<const float4*>(x);
    uint2* xh2 = reinterpret_cast<uint2*>(g_xh);
    const int n4 = (G_DATA * FEAT) / 4;               // 8.39M
#pragma unroll
    for (int k = 0; k < 8; k++) {
        int j = i + k * NEDGE;
        if (j < n4) {
            float4 v = __ldcs(&x4[j]);
            __half2 h01 = __floats2half2_rn(v.x, v.y);
            __half2 h23 = __floats2half2_rn(v.z, v.w);
            xh2[j] = make_uint2(*reinterpret_cast<unsigned*>(&h01),
                                *reinterpret_cast<unsigned*>(&h23));
        }
    }
}

// ---------------- gather-only projections ------------------------------------
// One warp per destination row. Edge records are preloaded cooperatively
// (lane l reads edges[beg+base+l]; 1 coalesced load per 32 edges), then the
// two half-warps gather two different source rows per iteration, 16 lanes x
// uint4 (16B) per 256B fp16 row. Inactive tail edges use w=0 (branch-free).

__device__ __forceinline__ void gather_accum_halfwarp(
    const uint4* __restrict__ rows,   // fp16 matrix as 16 uint4 per row
    const int2* __restrict__ edges,
    int beg, int cnt, int lane, float* acc, float& sw)
{
    int half = lane >> 4;             // which edge of the pair
    int hl   = lane & 15;             // 16B chunk within the row
    for (int base = 0; base < cnt; base += 32) {
        int nb = min(32, cnt - base);
        int2 rec = make_int2(0, 0);
        if (lane < nb) rec = __ldg(&edges[beg + base + lane]);
#pragma unroll 2
        for (int k = 0; 2 * k < nb; k++) {
            int e = 2 * k + half;                      // 0..31
            int  srcj = __shfl_sync(0xffffffffu, rec.x, e);
            int  wbit = __shfl_sync(0xffffffffu, rec.y, e);
            float wj = (e < nb) ? __int_as_float(wbit) : 0.f;
            uint4 p = __ldg(&rows[(size_t)srcj * 16 + hl]);
            float2 f0 = __half22float2(*reinterpret_cast<__half2*>(&p.x));
            float2 f1 = __half22float2(*reinterpret_cast<__half2*>(&p.y));
            float2 f2 = __half22float2(*reinterpret_cast<__half2*>(&p.z));
            float2 f3 = __half22float2(*reinterpret_cast<__half2*>(&p.w));
            sw += wj;
            acc[0] = fmaf(wj, f0.x, acc[0]);
            acc[1] = fmaf(wj, f0.y, acc[1]);
            acc[2] = fmaf(wj, f1.x, acc[2]);
            acc[3] = fmaf(wj, f1.y, acc[3]);
            acc[4] = fmaf(wj, f2.x, acc[4]);
            acc[5] = fmaf(wj, f2.y, acc[5]);
            acc[6] = fmaf(wj, f3.x, acc[6]);
            acc[7] = fmaf(wj, f3.y, acc[7]);
        }
    }
    // combine the two half-warps (lane i += lane i+16)
#pragma unroll
    for (int i = 0; i < 8; i++)
        acc[i] += __shfl_down_sync(0xffffffffu, acc[i], 16);
    sw += __shfl_down_sync(0xffffffffu, sw, 16);
}

// Down: gather from g_xh, store fp16 row into g_xc (lanes 0-15, uint4 each).
__global__ void __launch_bounds__(256) down_csr_kernel() {
    int g = (blockIdx.x * blockDim.x + threadIdx.x) >> 5;
    int lane = threadIdx.x & 31;
    if (g >= G_TRUNC) return;
    int beg = g_off_down[g];
    int cnt = g_off_down[g + 1] - beg;
    float acc[8] = {0.f, 0.f, 0.f, 0.f, 0.f, 0.f, 0.f, 0.f};
    float sw = 0.f;
    gather_accum_halfwarp(reinterpret_cast<const uint4*>(g_xh),
                          g_edges_down, beg, cnt, lane, acc, sw);
    if (lane < 16) {
        float inv = 1.f / fmaxf(sw, EPSV);
        __half2 h0 = __floats2half2_rn(acc[0] * inv, acc[1] * inv);
        __half2 h1 = __floats2half2_rn(acc[2] * inv, acc[3] * inv);
        __half2 h2 = __floats2half2_rn(acc[4] * inv, acc[5] * inv);
        __half2 h3 = __floats2half2_rn(acc[6] * inv, acc[7] * inv);
        uint4 packed = make_uint4(*reinterpret_cast<unsigned*>(&h0),
                                  *reinterpret_cast<unsigned*>(&h1),
                                  *reinterpret_cast<unsigned*>(&h2),
                                  *reinterpret_cast<unsigned*>(&h3));
        reinterpret_cast<uint4*>(g_xc + (size_t)g * FEAT)[lane] = packed;
    }
}

// Up: gather from g_xc, store fp32 row to out (lanes 0-15, 2x float4 each).
__global__ void __launch_bounds__(256) up_csr_kernel(float* __restrict__ out) {
    int g = (blockIdx.x * blockDim.x + threadIdx.x) >> 5;
    int lane = threadIdx.x & 31;
    if (g >= G_DATA) return;
    int beg = g_off_up[g];
    int cnt = g_off_up[g + 1] - beg;
    float acc[8] = {0.f, 0.f, 0.f, 0.f, 0.f, 0.f, 0.f, 0.f};
    float sw = 0.f;
    gather_accum_halfwarp(reinterpret_cast<const uint4*>(g_xc),
                          g_edges_up, beg, cnt, lane, acc, sw);
    if (lane < 16) {
        float inv = 1.f / fmaxf(sw, EPSV);
        float4* o = reinterpret_cast<float4*>(out + (size_t)g * FEAT) + lane * 2;
        __stcs(o,     make_float4(acc[0] * inv, acc[1] * inv, acc[2] * inv, acc[3] * inv));
        __stcs(o + 1, make_float4(acc[4] * inv, acc[5] * inv, acc[6] * inv, acc[7] * inv));
    }
}

// ---------------- launch -----------------------------------------------------

extern "C" void kernel_launch(void* const* d_in, const int* in_sizes, int n_in,
                              void* d_out, int out_size) {
    const float* x        = (const float*)d_in[0];   // (1,2,1,G_DATA,FEAT)
    const int*   down_src = (const int*)  d_in[1];
    const int*   down_dst = (const int*)  d_in[2];
    const float* down_w   = (const float*)d_in[3];
    const int*   up_src   = (const int*)  d_in[4];
    const int*   up_dst   = (const int*)  d_in[5];
    const float* up_w     = (const float*)d_in[6];
    float* out = (float*)d_out;
    (void)in_sizes; (void)n_in; (void)out_size;

    // x[:, -1, ...] slice = second half along dim 1.
    const float* x_slice = x + (size_t)G_DATA * FEAT;

    // CSR build (counters are zero at entry — countdown invariant)
    hist_kernel<<<NEDGE / 256, 256>>>(down_dst, up_dst);
    scan_partial_both<<<NBLK_DOWN + NBLK_UP, 256>>>();
    scan_final_both<<<NBLK_DOWN + NBLK_UP, 256>>>();
    scatter_convert_kernel<<<NEDGE / 256, 256>>>(down_src, down_dst, down_w,
                                                 up_src, up_dst, up_w, x_slice);
    // Gather-only projections
    down_csr_kernel<<<(G_TRUNC + 7) / 8, 256>>>();
    up_csr_kernel<<<G_DATA / 8, 256>>>(out);
}

// round 9
// speedup vs baseline: 1.1893x; 1.1893x over previous
#include <cuda_runtime.h>
#include <cuda_fp16.h>
#include <cstdint>

#define G_DATA  262144
#define G_TRUNC 40000
#define NEDGE   1048576
#define FEAT    128
#define EPSV    1e-8f

#define NBLK_DOWN 40     // ceil(G_TRUNC/1024)
#define NBLK_UP   256    // G_DATA/1024

// ---------------- scratch (__device__ globals; no allocation allowed) --------
// INVARIANT: g_cnt_* are zero at entry to kernel_launch. They start zero
// (static init) and the countdown scatter returns them to zero every call.
__device__ __half g_xh[(size_t)G_DATA * FEAT];        // 67 MB fp16 copy of x slice
__device__ __half g_xc[(size_t)G_TRUNC * FEAT];       // 10.2 MB fp16 intermediate
__device__ int   g_cnt_down[G_TRUNC];
__device__ int   g_cnt_up[G_DATA];
__device__ int   g_off_down[G_TRUNC + 1];
__device__ int   g_off_up[G_DATA + 1];
__device__ int   g_bsum_down[NBLK_DOWN];
__device__ int   g_bsum_up[NBLK_UP];
__device__ int2  g_edges_down[NEDGE];                 // (src, w bits) bucketed by dst
__device__ int2  g_edges_up[NEDGE];

// ---------------- CSR build --------------------------------------------------

__global__ void hist_kernel(const int* __restrict__ ddst, const int* __restrict__ udst) {
    int i = blockIdx.x * blockDim.x + threadIdx.x;
    if (i < NEDGE) {
        atomicAdd(&g_cnt_down[ddst[i]], 1);
        atomicAdd(&g_cnt_up[udst[i]], 1);
    }
}

// Per-1024-chunk sums for both arrays in one launch (blocks [0,40)=down).
__global__ void scan_partial_both() {
    __shared__ int red[256];
    int blk = blockIdx.x;
    const int* cnt; int* bsum; int n; int b;
    if (blk < NBLK_DOWN) { cnt = g_cnt_down; bsum = g_bsum_down; n = G_TRUNC; b = blk; }
    else                 { cnt = g_cnt_up;   bsum = g_bsum_up;   n = G_DATA;  b = blk - NBLK_DOWN; }
    int base = b * 1024 + threadIdx.x * 4;
    int s = 0;
#pragma unroll
    for (int j = 0; j < 4; j++) { int i = base + j; if (i < n) s += cnt[i]; }
    red[threadIdx.x] = s;
    __syncthreads();
    for (int off = 128; off > 0; off >>= 1) {
        if (threadIdx.x < off) red[threadIdx.x] += red[threadIdx.x + off];
        __syncthreads();
    }
    if (threadIdx.x == 0) bsum[b] = red[0];
}

// Per-element exclusive scan. Each block redundantly scans the (<=256) block
// sums itself. cnt is left intact (the scatter's countdown cursor consumes it).
__global__ void scan_final_both() {
    int blk = blockIdx.x;
    const int* cnt; int* off; const int* bsum; int n, nblk, b;
    if (blk < NBLK_DOWN) { cnt = g_cnt_down; off = g_off_down; bsum = g_bsum_down;
                           n = G_TRUNC; nblk = NBLK_DOWN; b = blk; }
    else                 { cnt = g_cnt_up;   off = g_off_up;   bsum = g_bsum_up;
                           n = G_DATA;  nblk = NBLK_UP;   b = blk - NBLK_DOWN; }
    int t = threadIdx.x;
    int lane = t & 31, wid = t >> 5;

    __shared__ int s[256];
    int bv = (t < nblk) ? bsum[t] : 0;
    s[t] = bv;
    __syncthreads();
    for (int o = 1; o < 256; o <<= 1) {
        int add = (t >= o) ? s[t - o] : 0;
        __syncthreads();
        s[t] += add;
        __syncthreads();
    }
    int block_off = (b > 0) ? s[b - 1] : 0;
    if (b == 0 && t == 0) off[n] = s[nblk - 1];   // grand total

    int base = b * 1024 + t * 4;
    int v0 = 0, v1 = 0, v2 = 0, v3 = 0;
    if (base + 0 < n) v0 = cnt[base + 0];
    if (base + 1 < n) v1 = cnt[base + 1];
    if (base + 2 < n) v2 = cnt[base + 2];
    if (base + 3 < n) v3 = cnt[base + 3];
    int tsum = v0 + v1 + v2 + v3;
    int x = tsum;
#pragma unroll
    for (int o = 1; o < 32; o <<= 1) {
        int y = __shfl_up_sync(0xffffffffu, x, o);
        if (lane >= o) x += y;
    }
    __shared__ int wsum[8];
    if (lane == 31) wsum[wid] = x;
    __syncthreads();
    if (t == 0) {
        int run = 0;
#pragma unroll
        for (int i = 0; i < 8; i++) { int tmp = wsum[i]; wsum[i] = run; run += tmp; }
    }
    __syncthreads();
    int excl = block_off + wsum[wid] + (x - tsum);
    if (base + 0 < n) off[base + 0] = excl; excl += v0;
    if (base + 1 < n) off[base + 1] = excl; excl += v1;
    if (base + 2 < n) off[base + 2] = excl; excl += v2;
    if (base + 3 < n) off[base + 3] = excl;
}

// Fused scatter + fp32->fp16 convert. Countdown cursor leaves cnt at zero.
__global__ void __launch_bounds__(256) scatter_convert_kernel(
    const int* __restrict__ dsrc, const int* __restrict__ ddst,
    const float* __restrict__ dw,
    const int* __restrict__ usrc, const int* __restrict__ udst,
    const float* __restrict__ uw,
    const float* __restrict__ x)
{
    int i = blockIdx.x * blockDim.x + threadIdx.x;

    {
        int d = ddst[i];
        int idx = atomicAdd(&g_cnt_down[d], -1);
        g_edges_down[g_off_down[d] + idx - 1] = make_int2(dsrc[i], __float_as_int(dw[i]));
    }
    {
        int d = udst[i];
        int idx = atomicAdd(&g_cnt_up[d], -1);
        g_edges_up[g_off_up[d] + idx - 1] = make_int2(usrc[i], __float_as_int(uw[i]));
    }

    const float4* x4 = reinterpret_cast<const float4*>(x);
    uint2* xh2 = reinterpret_cast<uint2*>(g_xh);
    const int n4 = (G_DATA * FEAT) / 4;               // 8.39M
#pragma unroll
    for (int k = 0; k < 8; k++) {
        int j = i + k * NEDGE;
        if (j < n4) {
            float4 v = __ldcs(&x4[j]);
            __half2 h01 = __floats2half2_rn(v.x, v.y);
            __half2 h23 = __floats2half2_rn(v.z, v.w);
            xh2[j] = make_uint2(*reinterpret_cast<unsigned*>(&h01),
                                *reinterpret_cast<unsigned*>(&h23));
        }
    }
}

// ---------------- gather-only projections ------------------------------------
// Round-7 structure (per-lane uint2, warp-wide 256B row per gather), unroll
// deepened 4 -> 8 for 2KB/warp of outstanding gathers.

__device__ __forceinline__ float4 h4_to_f4(uint2 p) {
    float2 a = __half22float2(*reinterpret_cast<__half2*>(&p.x));
    float2 b = __half22float2(*reinterpret_cast<__half2*>(&p.y));
    return make_float4(a.x, a.y, b.x, b.y);
}

__device__ __forceinline__ void accum1(float4& acc, float& sw, float w, float4 v) {
    sw += w;
    acc.x = fmaf(w, v.x, acc.x);
    acc.y = fmaf(w, v.y, acc.y);
    acc.z = fmaf(w, v.z, acc.z);
    acc.w = fmaf(w, v.w, acc.w);
}

__device__ __forceinline__ void segment_reduce8(
    const uint2* __restrict__ rows, const int2* __restrict__ edges,
    int beg, int end, int lane, float4& acc, float& sw)
{
    int e = beg;
    for (; e + 7 < end; e += 8) {
        int2 r[8];
#pragma unroll
        for (int k = 0; k < 8; k++) r[k] = edges[e + k];
        uint2 p[8];
#pragma unroll
        for (int k = 0; k < 8; k++)
            p[k] = __ldg(&rows[(size_t)r[k].x * (FEAT / 4) + lane]);
#pragma unroll
        for (int k = 0; k < 8; k++)
            accum1(acc, sw, __int_as_float(r[k].y), h4_to_f4(p[k]));
    }
    for (; e < end; e++) {
        int2 r0 = edges[e];
        float4 v = h4_to_f4(__ldg(&rows[(size_t)r0.x * (FEAT / 4) + lane]));
        accum1(acc, sw, __int_as_float(r0.y), v);
    }
}

// Down: one warp per truncated row. fp16 gather, fp32 accumulate, fp16 store.
__global__ void __launch_bounds__(256) down_csr_kernel() {
    int g = (blockIdx.x * blockDim.x + threadIdx.x) >> 5;
    int lane = threadIdx.x & 31;
    if (g >= G_TRUNC) return;
    int beg = g_off_down[g];
    int end = g_off_down[g + 1];
    float4 acc = make_float4(0.f, 0.f, 0.f, 0.f);
    float sw = 0.f;
    segment_reduce8(reinterpret_cast<const uint2*>(g_xh),
                    g_edges_down, beg, end, lane, acc, sw);
    float inv = 1.f / fmaxf(sw, EPSV);
    __half2 h01 = __floats2half2_rn(acc.x * inv, acc.y * inv);
    __half2 h23 = __floats2half2_rn(acc.z * inv, acc.w * inv);
    reinterpret_cast<uint2*>(g_xc + (size_t)g * FEAT)[lane] =
        make_uint2(*reinterpret_cast<unsigned*>(&h01),
                   *reinterpret_cast<unsigned*>(&h23));
}

// Up: one warp per data row. fp16 gather of xc, fp32 accumulate, streaming store.
__global__ void __launch_bounds__(256) up_csr_kernel(float* __restrict__ out) {
    int g = (blockIdx.x * blockDim.x + threadIdx.x) >> 5;
    int lane = threadIdx.x & 31;
    if (g >= G_DATA) return;
    int beg = g_off_up[g];
    int end = g_off_up[g + 1];
    float4 acc = make_float4(0.f, 0.f, 0.f, 0.f);
    float sw = 0.f;
    segment_reduce8(reinterpret_cast<const uint2*>(g_xc),
                    g_edges_up, beg, end, lane, acc, sw);
    float inv = 1.f / fmaxf(sw, EPSV);
    __stcs(reinterpret_cast<float4*>(out + (size_t)g * FEAT) + lane,
           make_float4(acc.x * inv, acc.y * inv, acc.z * inv, acc.w * inv));
}

// ---------------- launch -----------------------------------------------------

extern "C" void kernel_launch(void* const* d_in, const int* in_sizes, int n_in,
                              void* d_out, int out_size) {
    const float* x        = (const float*)d_in[0];   // (1,2,1,G_DATA,FEAT)
    const int*   down_src = (const int*)  d_in[1];
    const int*   down_dst = (const int*)  d_in[2];
    const float* down_w   = (const float*)d_in[3];
    const int*   up_src   = (const int*)  d_in[4];
    const int*   up_dst   = (const int*)  d_in[5];
    const float* up_w     = (const float*)d_in[6];
    float* out = (float*)d_out;
    (void)in_sizes; (void)n_in; (void)out_size;

    // x[:, -1, ...] slice = second half along dim 1.
    const float* x_slice = x + (size_t)G_DATA * FEAT;

    // CSR build (counters are zero at entry — countdown invariant)
    hist_kernel<<<NEDGE / 256, 256>>>(down_dst, up_dst);
    scan_partial_both<<<NBLK_DOWN + NBLK_UP, 256>>>();
    scan_final_both<<<NBLK_DOWN + NBLK_UP, 256>>>();
    scatter_convert_kernel<<<NEDGE / 256, 256>>>(down_src, down_dst, down_w,
                                                 up_src, up_dst, up_w, x_slice);
    // Gather-only projections
    down_csr_kernel<<<(G_TRUNC + 7) / 8, 256>>>();
    up_csr_kernel<<<G_DATA / 8, 256>>>(out);
}